// round 5
// baseline (speedup 1.0000x reference)
#include <cuda_runtime.h>
#include <math.h>

#define NN 50000
#define FD 128
#define NC 16
#define MAXE 800000

// Scratch (device globals: no allocation allowed anywhere)
__device__ float g_h[NN * FD];      // GEMM output of current layer
__device__ float g_a[NN * FD];      // aggregated output -> input of next layer
__device__ float g_h16[NN * NC];    // last-layer GEMM output
__device__ float g_dinv[NN];        // deg^{-1/2}
__device__ int   g_src[MAXE];       // decoded edge sources
__device__ int   g_dst[MAXE];       // decoded edge destinations
__device__ float g_norm[MAXE];      // per-edge coefficient dinv[src]*dinv[dst]
__device__ int   g_is64;            // 1 if edge_index is int64, 0 if int32

// ---------------------------------------------------------------- edge dtype detect
// int64 layout: words [lo0,hi0,lo1,hi1,...], hi words all 0 (ids < 2^31).
// int32 layout: words are node ids; odd words ~U[0,50000) -> some nonzero.
__global__ void k_detect(const int* __restrict__ w, int E) {
    __shared__ int any;
    if (threadIdx.x == 0) any = 0;
    __syncthreads();
    int n = E < 2048 ? E : 2048;
    for (int i = threadIdx.x; i < n; i += 256)
        if (w[2 * i + 1] != 0) any = 1;
    __syncthreads();
    if (threadIdx.x == 0) g_is64 = (any ? 0 : 1);
}

__global__ void k_zero_deg(int n) {
    int i = blockIdx.x * blockDim.x + threadIdx.x;
    if (i < n) g_dinv[i] = 0.0f;
}

// decode edges (either dtype) + accumulate in-degree
__global__ void k_convert(const int* __restrict__ w, int E) {
    int e = blockIdx.x * blockDim.x + threadIdx.x;
    if (e >= E) return;
    int s, d;
    if (g_is64) { s = w[2 * e];  d = w[2 * E + 2 * e]; }  // low words of int64
    else        { s = w[e];      d = w[E + e]; }
    g_src[e] = s;
    g_dst[e] = d;
    atomicAdd(&g_dinv[d], 1.0f);
}

__global__ void k_dinv(int n) {
    int i = blockIdx.x * blockDim.x + threadIdx.x;
    if (i < n) g_dinv[i] = rsqrtf(g_dinv[i] + 2.0f);   // improved=True: +2 self-loop
}

__global__ void k_norm(int E) {
    int e = blockIdx.x * blockDim.x + threadIdx.x;
    if (e < E) g_norm[e] = g_dinv[g_src[e]] * g_dinv[g_dst[e]];
}

// ---------------------------------------------------------------- GEMM 128x128
// g_h[M,128] = act(A[M,128]) @ W[128,128]
// BM=64. W fully staged in smem (64KB) + A tile (32KB). 256 threads.
template <bool RELU, bool FROM_PARAM>
__global__ __launch_bounds__(256, 2) void k_gemm128(
    const float4* __restrict__ Ain, const float4* __restrict__ W, int M)
{
    extern __shared__ float smem[];
    float* Ws = smem;              // 128*128
    float* As = smem + FD * FD;    // 64*128
    const int tid = threadIdx.x;
    const int row0 = blockIdx.x * 64;

    const float4* A = FROM_PARAM ? Ain : (const float4*)g_a;

    float4* Ws4 = (float4*)Ws;
    #pragma unroll
    for (int i = tid; i < FD * FD / 4; i += 256) Ws4[i] = W[i];

    float4* As4 = (float4*)As;
    #pragma unroll
    for (int i = tid; i < 64 * FD / 4; i += 256) {
        int r = i >> 5, c = i & 31;
        int gr = row0 + r;
        float4 v = make_float4(0.f, 0.f, 0.f, 0.f);
        if (gr < M) {
            v = A[gr * 32 + c];
            if (RELU) {
                v.x = fmaxf(v.x, 0.f); v.y = fmaxf(v.y, 0.f);
                v.z = fmaxf(v.z, 0.f); v.w = fmaxf(v.w, 0.f);
            }
        }
        As4[i] = v;
    }
    __syncthreads();

    const int tr = tid >> 5, lane = tid & 31;
    float4 acc[8];
    #pragma unroll
    for (int i = 0; i < 8; i++) acc[i] = make_float4(0.f, 0.f, 0.f, 0.f);

    const float* arow = As + tr * 8 * FD;
    const float4* Wc = (const float4*)Ws;

    #pragma unroll 8
    for (int k = 0; k < FD; k++) {
        float4 b = Wc[k * 32 + lane];
        #pragma unroll
        for (int i = 0; i < 8; i++) {
            float a = arow[i * FD + k];
            acc[i].x += a * b.x; acc[i].y += a * b.y;
            acc[i].z += a * b.z; acc[i].w += a * b.w;
        }
    }

    #pragma unroll
    for (int i = 0; i < 8; i++) {
        int gr = row0 + tr * 8 + i;
        if (gr < M) ((float4*)g_h)[gr * 32 + lane] = acc[i];
    }
}

// ---------------------------------------------------------------- GEMM 128x16 (last layer)
// g_h16[M,16] = relu(g_a[M,128]) @ W3[128,16]
__global__ __launch_bounds__(256) void k_gemm16(const float* __restrict__ W, int M)
{
    __shared__ float Ws[FD * NC];   // 8KB
    __shared__ float Xs[16 * FD];   // 8KB
    const int tid = threadIdx.x;
    const int row0 = blockIdx.x * 16;

    #pragma unroll
    for (int i = tid; i < FD * NC / 4; i += 256)
        ((float4*)Ws)[i] = ((const float4*)W)[i];
    #pragma unroll
    for (int i = tid; i < 16 * FD / 4; i += 256) {
        int r = i >> 5, c = i & 31;
        int gr = row0 + r;
        float4 v = make_float4(0.f, 0.f, 0.f, 0.f);
        if (gr < M) {
            v = ((const float4*)g_a)[gr * 32 + c];
            v.x = fmaxf(v.x, 0.f); v.y = fmaxf(v.y, 0.f);
            v.z = fmaxf(v.z, 0.f); v.w = fmaxf(v.w, 0.f);
        }
        ((float4*)Xs)[i] = v;
    }
    __syncthreads();

    const int r = tid >> 4, c = tid & 15;
    float acc = 0.f;
    #pragma unroll 8
    for (int k = 0; k < FD; k++) acc += Xs[r * FD + k] * Ws[k * NC + c];

    int gr = row0 + r;
    if (gr < M) g_h16[gr * NC + c] = acc;
}

// ---------------------------------------------------------------- pre: g_a = 2*dinv^2*g_h + b
__global__ void k_pre128(const float4* __restrict__ b, int N)
{
    int i = blockIdx.x * blockDim.x + threadIdx.x;   // over N*32 float4s
    if (i >= N * 32) return;
    int node = i >> 5, c = i & 31;
    float d = g_dinv[node];
    float s = 2.0f * d * d;
    float4 hv = ((const float4*)g_h)[i], bv = b[c];
    ((float4*)g_a)[i] = make_float4(hv.x * s + bv.x, hv.y * s + bv.y,
                                    hv.z * s + bv.z, hv.w * s + bv.w);
}

// out = 2*dinv^2*g_h16 + b3
__global__ void k_pre16(const float4* __restrict__ b, float4* __restrict__ out, int N)
{
    int i = blockIdx.x * blockDim.x + threadIdx.x;   // over N*4 float4s
    if (i >= N * 4) return;
    int node = i >> 2, c = i & 3;
    float d = g_dinv[node];
    float s = 2.0f * d * d;
    float4 hv = ((const float4*)g_h16)[i], bv = b[c];
    out[i] = make_float4(hv.x * s + bv.x, hv.y * s + bv.y,
                         hv.z * s + bv.z, hv.w * s + bv.w);
}

// ---------------------------------------------------------------- edge scatter
// warp per edge: g_a[dst] += norm * g_h[src], 128 floats = 32 lanes x float4
__global__ void k_scatter128(int E)
{
    int warp = (blockIdx.x * blockDim.x + threadIdx.x) >> 5;
    int lane = threadIdx.x & 31;
    if (warp >= E) return;
    int src = g_src[warp];
    int dst = g_dst[warp];
    float norm = g_norm[warp];
    float4 v = ((const float4*)g_h)[src * 32 + lane];
    float4* p = ((float4*)g_a) + dst * 32 + lane;
    atomicAdd(p, make_float4(v.x * norm, v.y * norm, v.z * norm, v.w * norm));
}

// 4 lanes per edge: out[dst] += norm * g_h16[src], 16 floats = 4 x float4
__global__ void k_scatter16(float* __restrict__ out, int E)
{
    int t = blockIdx.x * blockDim.x + threadIdx.x;
    int e = t >> 2, q = t & 3;
    if (e >= E) return;
    int src = g_src[e];
    int dst = g_dst[e];
    float norm = g_norm[e];
    float4 v = ((const float4*)g_h16)[src * 4 + q];
    float4* p = ((float4*)out) + dst * 4 + q;
    atomicAdd(p, make_float4(v.x * norm, v.y * norm, v.z * norm, v.w * norm));
}

__global__ void k_tanh(float* o, int n) {
    int i = blockIdx.x * blockDim.x + threadIdx.x;
    if (i < n) o[i] = tanhf(o[i]);
}

// ---------------------------------------------------------------- launch
extern "C" void kernel_launch(void* const* d_in, const int* in_sizes, int n_in,
                              void* d_out, int out_size)
{
    const float* x  = (const float*)d_in[0];
    const int*   ew = (const int*)d_in[1];   // edge_index words (dtype auto-detected)
    const float* W0 = (const float*)d_in[2];
    const float* b0 = (const float*)d_in[3];
    const float* W1 = (const float*)d_in[4];
    const float* b1 = (const float*)d_in[5];
    const float* W2 = (const float*)d_in[6];
    const float* b2 = (const float*)d_in[7];
    const float* W3 = (const float*)d_in[8];
    const float* b3 = (const float*)d_in[9];
    float* out = (float*)d_out;

    const int E = in_sizes[1] / 2;     // element count -> edges, dtype-independent
    const int M = in_sizes[0] / FD;    // 50000

    const size_t SMEM = (size_t)(FD * FD + 64 * FD) * sizeof(float);  // 96KB
    cudaFuncSetAttribute(k_gemm128<false, true>,  cudaFuncAttributeMaxDynamicSharedMemorySize, (int)SMEM);
    cudaFuncSetAttribute(k_gemm128<true,  false>, cudaFuncAttributeMaxDynamicSharedMemorySize, (int)SMEM);

    // ---- graph prep (identical across layers) ----
    k_detect<<<1, 256>>>(ew, E);
    k_zero_deg<<<(M + 255) / 256, 256>>>(M);
    k_convert<<<(E + 255) / 256, 256>>>(ew, E);
    k_dinv<<<(M + 255) / 256, 256>>>(M);
    k_norm<<<(E + 255) / 256, 256>>>(E);

    const int gGemm = (M + 63) / 64;
    const int gPre128 = (M * 32 + 255) / 256;
    const int gScat128 = (E + 7) / 8;          // 8 warps/block, warp per edge

    // Layer 0 (input: raw x, no relu)
    k_gemm128<false, true><<<gGemm, 256, SMEM>>>((const float4*)x, (const float4*)W0, M);
    k_pre128<<<gPre128, 256>>>((const float4*)b0, M);
    k_scatter128<<<gScat128, 256>>>(E);

    // Layer 1 (relu folded into GEMM A-load)
    k_gemm128<true, false><<<gGemm, 256, SMEM>>>(nullptr, (const float4*)W1, M);
    k_pre128<<<gPre128, 256>>>((const float4*)b1, M);
    k_scatter128<<<gScat128, 256>>>(E);

    // Layer 2
    k_gemm128<true, false><<<gGemm, 256, SMEM>>>(nullptr, (const float4*)W2, M);
    k_pre128<<<gPre128, 256>>>((const float4*)b2, M);
    k_scatter128<<<gScat128, 256>>>(E);

    // Layer 3 (16-wide) -> d_out, then tanh
    k_gemm16<<<(M + 15) / 16, 256>>>(W3, M);
    k_pre16<<<(M * 4 + 255) / 256, 256>>>((const float4*)b3, (float4*)out, M);
    k_scatter16<<<(E * 4 + 255) / 256, 256>>>(out, E);
    k_tanh<<<(M * NC + 255) / 256, 256>>>(out, M * NC);
}

// round 6
// speedup vs baseline: 2.2812x; 2.2812x over previous
#include <cuda_runtime.h>
#include <math.h>

#define NN 50000
#define FD 128
#define NC 16
#define MAXE 800000
#define SCAN_B 512

// Scratch (device globals: no allocation allowed anywhere)
__device__ float g_h[NN * FD];        // GEMM output of current layer
__device__ float g_a[NN * FD];        // aggregated output -> input of next layer
__device__ float g_h16[NN * NC];      // last-layer GEMM output
__device__ float g_dinv[NN];          // deg^{-1/2}
__device__ int   g_src[MAXE];         // decoded edge sources
__device__ int   g_dst[MAXE];         // decoded edge destinations
__device__ int   g_cnt[NN];           // in-degree counts
__device__ int   g_tmp[NN];           // block-local exclusive scan
__device__ int   g_bsum[128];         // per-block sums for scan
__device__ int   g_rowptr[NN + 1];    // CSR row pointers
__device__ int   g_cursor[NN];        // fill cursors
__device__ int2  g_csr[MAXE];         // packed {src, __float_as_int(norm)}
__device__ int   g_is64;              // edge dtype flag

// ---------------------------------------------------------------- edge dtype detect
__global__ void k_detect(const int* __restrict__ w, int E) {
    __shared__ int any;
    if (threadIdx.x == 0) any = 0;
    __syncthreads();
    int n = E < 2048 ? E : 2048;
    for (int i = threadIdx.x; i < n; i += 256)
        if (w[2 * i + 1] != 0) any = 1;
    __syncthreads();
    if (threadIdx.x == 0) g_is64 = (any ? 0 : 1);
}

__global__ void k_zero_cnt(int n) {
    int i = blockIdx.x * blockDim.x + threadIdx.x;
    if (i < n) g_cnt[i] = 0;
}

// decode edges (either dtype) + count in-degree
__global__ void k_convert(const int* __restrict__ w, int E) {
    int e = blockIdx.x * blockDim.x + threadIdx.x;
    if (e >= E) return;
    int s, d;
    if (g_is64) { s = w[2 * e]; d = w[2 * E + 2 * e]; }   // low words of int64
    else        { s = w[e];     d = w[E + e]; }
    g_src[e] = s;
    g_dst[e] = d;
    atomicAdd(&g_cnt[d], 1);
}

__global__ void k_dinv(int n) {
    int i = blockIdx.x * blockDim.x + threadIdx.x;
    if (i < n) g_dinv[i] = rsqrtf((float)g_cnt[i] + 2.0f);   // improved: +2 self-loop
}

// ---------------------------------------------------------------- 3-kernel exclusive scan of g_cnt
__global__ void k_scan1(int n) {            // SCAN_B threads per block
    __shared__ int sh[SCAN_B];
    int i = blockIdx.x * SCAN_B + threadIdx.x;
    int v = (i < n) ? g_cnt[i] : 0;
    sh[threadIdx.x] = v;
    __syncthreads();
    for (int off = 1; off < SCAN_B; off <<= 1) {
        int t = (threadIdx.x >= off) ? sh[threadIdx.x - off] : 0;
        __syncthreads();
        sh[threadIdx.x] += t;
        __syncthreads();
    }
    if (i < n) g_tmp[i] = sh[threadIdx.x] - v;           // exclusive within block
    if (threadIdx.x == SCAN_B - 1) g_bsum[blockIdx.x] = sh[SCAN_B - 1];
}

__global__ void k_scan2(int nb) {           // single block, 128 threads, nb <= 128
    __shared__ int sh[128];
    int v = (threadIdx.x < nb) ? g_bsum[threadIdx.x] : 0;
    sh[threadIdx.x] = v;
    __syncthreads();
    for (int off = 1; off < 128; off <<= 1) {
        int t = (threadIdx.x >= off) ? sh[threadIdx.x - off] : 0;
        __syncthreads();
        sh[threadIdx.x] += t;
        __syncthreads();
    }
    if (threadIdx.x < nb) g_bsum[threadIdx.x] = sh[threadIdx.x] - v;  // exclusive
}

__global__ void k_scan3(int n, int E) {
    int i = blockIdx.x * blockDim.x + threadIdx.x;
    if (i < n) {
        int r = g_tmp[i] + g_bsum[i / SCAN_B];
        g_rowptr[i] = r;
        g_cursor[i] = r;
    }
    if (i == 0) g_rowptr[n] = E;
}

// fill CSR: packed {src, norm}
__global__ void k_fill(int E) {
    int e = blockIdx.x * blockDim.x + threadIdx.x;
    if (e >= E) return;
    int s = g_src[e], d = g_dst[e];
    int pos = atomicAdd(&g_cursor[d], 1);
    float nrm = g_dinv[s] * g_dinv[d];
    g_csr[pos] = make_int2(s, __float_as_int(nrm));
}

// ---------------------------------------------------------------- GEMM 128x128
// g_h[M,128] = act(A[M,128]) @ W[128,128].  BM=64, W fully staged in smem.
template <bool RELU, bool FROM_PARAM>
__global__ __launch_bounds__(256, 2) void k_gemm128(
    const float4* __restrict__ Ain, const float4* __restrict__ W, int M)
{
    extern __shared__ float smem[];
    float* Ws = smem;              // 128*128
    float* As = smem + FD * FD;    // 64*128
    const int tid = threadIdx.x;
    const int row0 = blockIdx.x * 64;

    const float4* A = FROM_PARAM ? Ain : (const float4*)g_a;

    float4* Ws4 = (float4*)Ws;
    #pragma unroll
    for (int i = tid; i < FD * FD / 4; i += 256) Ws4[i] = W[i];

    float4* As4 = (float4*)As;
    #pragma unroll
    for (int i = tid; i < 64 * FD / 4; i += 256) {
        int r = i >> 5, c = i & 31;
        int gr = row0 + r;
        float4 v = make_float4(0.f, 0.f, 0.f, 0.f);
        if (gr < M) {
            v = A[gr * 32 + c];
            if (RELU) {
                v.x = fmaxf(v.x, 0.f); v.y = fmaxf(v.y, 0.f);
                v.z = fmaxf(v.z, 0.f); v.w = fmaxf(v.w, 0.f);
            }
        }
        As4[i] = v;
    }
    __syncthreads();

    const int tr = tid >> 5, lane = tid & 31;
    float4 acc[8];
    #pragma unroll
    for (int i = 0; i < 8; i++) acc[i] = make_float4(0.f, 0.f, 0.f, 0.f);

    const float* arow = As + tr * 8 * FD;
    const float4* Wc = (const float4*)Ws;

    #pragma unroll 8
    for (int k = 0; k < FD; k++) {
        float4 b = Wc[k * 32 + lane];
        #pragma unroll
        for (int i = 0; i < 8; i++) {
            float a = arow[i * FD + k];
            acc[i].x += a * b.x; acc[i].y += a * b.y;
            acc[i].z += a * b.z; acc[i].w += a * b.w;
        }
    }

    #pragma unroll
    for (int i = 0; i < 8; i++) {
        int gr = row0 + tr * 8 + i;
        if (gr < M) ((float4*)g_h)[gr * 32 + lane] = acc[i];
    }
}

// ---------------------------------------------------------------- GEMM 128x16 (last layer)
__global__ __launch_bounds__(256) void k_gemm16(const float* __restrict__ W, int M)
{
    __shared__ float Ws[FD * NC];
    __shared__ float Xs[16 * FD];
    const int tid = threadIdx.x;
    const int row0 = blockIdx.x * 16;

    #pragma unroll
    for (int i = tid; i < FD * NC / 4; i += 256)
        ((float4*)Ws)[i] = ((const float4*)W)[i];
    #pragma unroll
    for (int i = tid; i < 16 * FD / 4; i += 256) {
        int r = i >> 5, c = i & 31;
        int gr = row0 + r;
        float4 v = make_float4(0.f, 0.f, 0.f, 0.f);
        if (gr < M) {
            v = ((const float4*)g_a)[gr * 32 + c];
            v.x = fmaxf(v.x, 0.f); v.y = fmaxf(v.y, 0.f);
            v.z = fmaxf(v.z, 0.f); v.w = fmaxf(v.w, 0.f);
        }
        ((float4*)Xs)[i] = v;
    }
    __syncthreads();

    const int r = tid >> 4, c = tid & 15;
    float acc = 0.f;
    #pragma unroll 8
    for (int k = 0; k < FD; k++) acc += Xs[r * FD + k] * Ws[k * NC + c];

    int gr = row0 + r;
    if (gr < M) g_h16[gr * NC + c] = acc;
}

// ---------------------------------------------------------------- fused aggregate (CSR, no atomics)
// one warp per node: g_a[n] = b + 2*dinv^2*g_h[n] + sum_{e in CSR[n]} norm_e * g_h[src_e]
__global__ __launch_bounds__(256) void k_agg128(const float4* __restrict__ b, int N)
{
    int warp = (blockIdx.x * blockDim.x + threadIdx.x) >> 5;
    int lane = threadIdx.x & 31;
    if (warp >= N) return;
    int beg = g_rowptr[warp], end = g_rowptr[warp + 1];
    float dv = g_dinv[warp];
    float s = 2.0f * dv * dv;
    const float4* h4 = (const float4*)g_h;

    float4 acc = h4[warp * 32 + lane];
    float4 bv = b[lane];
    acc.x = acc.x * s + bv.x; acc.y = acc.y * s + bv.y;
    acc.z = acc.z * s + bv.z; acc.w = acc.w * s + bv.w;

    int e = beg;
    for (; e + 1 < end; e += 2) {
        int2 c0 = g_csr[e], c1 = g_csr[e + 1];
        float4 v0 = h4[c0.x * 32 + lane];
        float4 v1 = h4[c1.x * 32 + lane];
        float n0 = __int_as_float(c0.y), n1 = __int_as_float(c1.y);
        acc.x += n0 * v0.x + n1 * v1.x;
        acc.y += n0 * v0.y + n1 * v1.y;
        acc.z += n0 * v0.z + n1 * v1.z;
        acc.w += n0 * v0.w + n1 * v1.w;
    }
    if (e < end) {
        int2 c0 = g_csr[e];
        float4 v0 = h4[c0.x * 32 + lane];
        float n0 = __int_as_float(c0.y);
        acc.x += n0 * v0.x; acc.y += n0 * v0.y;
        acc.z += n0 * v0.z; acc.w += n0 * v0.w;
    }
    ((float4*)g_a)[warp * 32 + lane] = acc;
}

// last layer: 4 lanes per node, fused bias + self-loop + aggregate + tanh -> out
__global__ __launch_bounds__(256) void k_agg16(const float4* __restrict__ b,
                                               float4* __restrict__ out, int N)
{
    int t = blockIdx.x * blockDim.x + threadIdx.x;
    int node = t >> 2, q = t & 3;
    if (node >= N) return;
    int beg = g_rowptr[node], end = g_rowptr[node + 1];
    float dv = g_dinv[node];
    float s = 2.0f * dv * dv;
    const float4* h4 = (const float4*)g_h16;

    float4 acc = h4[node * 4 + q];
    float4 bv = b[q];
    acc.x = acc.x * s + bv.x; acc.y = acc.y * s + bv.y;
    acc.z = acc.z * s + bv.z; acc.w = acc.w * s + bv.w;

    for (int e = beg; e < end; e++) {
        int2 c = g_csr[e];
        float4 v = h4[c.x * 4 + q];
        float n = __int_as_float(c.y);
        acc.x += n * v.x; acc.y += n * v.y;
        acc.z += n * v.z; acc.w += n * v.w;
    }
    acc.x = tanhf(acc.x); acc.y = tanhf(acc.y);
    acc.z = tanhf(acc.z); acc.w = tanhf(acc.w);
    out[node * 4 + q] = acc;
}

// ---------------------------------------------------------------- launch
extern "C" void kernel_launch(void* const* d_in, const int* in_sizes, int n_in,
                              void* d_out, int out_size)
{
    const float* x  = (const float*)d_in[0];
    const int*   ew = (const int*)d_in[1];   // edge_index words (dtype auto-detected)
    const float* W0 = (const float*)d_in[2];
    const float* b0 = (const float*)d_in[3];
    const float* W1 = (const float*)d_in[4];
    const float* b1 = (const float*)d_in[5];
    const float* W2 = (const float*)d_in[6];
    const float* b2 = (const float*)d_in[7];
    const float* W3 = (const float*)d_in[8];
    const float* b3 = (const float*)d_in[9];
    float* out = (float*)d_out;

    const int E = in_sizes[1] / 2;
    const int M = in_sizes[0] / FD;

    const size_t SMEM = (size_t)(FD * FD + 64 * FD) * sizeof(float);  // 96KB
    cudaFuncSetAttribute(k_gemm128<false, true>,  cudaFuncAttributeMaxDynamicSharedMemorySize, (int)SMEM);
    cudaFuncSetAttribute(k_gemm128<true,  false>, cudaFuncAttributeMaxDynamicSharedMemorySize, (int)SMEM);

    // ---- graph prep: decode + degrees + CSR (graph identical across layers) ----
    const int nb = (M + SCAN_B - 1) / SCAN_B;   // 98 blocks
    k_detect<<<1, 256>>>(ew, E);
    k_zero_cnt<<<(M + 255) / 256, 256>>>(M);
    k_convert<<<(E + 255) / 256, 256>>>(ew, E);
    k_dinv<<<(M + 255) / 256, 256>>>(M);
    k_scan1<<<nb, SCAN_B>>>(M);
    k_scan2<<<1, 128>>>(nb);
    k_scan3<<<(M + 255) / 256, 256>>>(M, E);
    k_fill<<<(E + 255) / 256, 256>>>(E);

    const int gGemm = (M + 63) / 64;
    const int gAgg128 = (M * 32 + 255) / 256;   // warp per node
    const int gAgg16  = (M * 4 + 255) / 256;    // 4 lanes per node

    // Layer 0
    k_gemm128<false, true><<<gGemm, 256, SMEM>>>((const float4*)x, (const float4*)W0, M);
    k_agg128<<<gAgg128, 256>>>((const float4*)b0, M);

    // Layer 1 (relu folded into GEMM A-load)
    k_gemm128<true, false><<<gGemm, 256, SMEM>>>(nullptr, (const float4*)W1, M);
    k_agg128<<<gAgg128, 256>>>((const float4*)b1, M);

    // Layer 2
    k_gemm128<true, false><<<gGemm, 256, SMEM>>>(nullptr, (const float4*)W2, M);
    k_agg128<<<gAgg128, 256>>>((const float4*)b2, M);

    // Layer 3 (16-wide) fused: gemm -> aggregate+bias+tanh -> out
    k_gemm16<<<(M + 15) / 16, 256>>>(W3, M);
    k_agg16<<<gAgg16, 256>>>((const float4*)b3, (float4*)out, M);
}

// round 9
// speedup vs baseline: 2.8482x; 1.2485x over previous
#include <cuda_runtime.h>
#include <cuda_bf16.h>
#include <math.h>
#include <cstdint>

#define NN 50000
#define FD 128
#define NC 16
#define MAXE 800000
#define SCAN_B 512

// ---------------------------------------------------------------- scratch
__device__ float g_h[NN * FD];                // GEMM output (fp32), consumed by aggregate
__device__ float g_h16[NN * NC];              // last-layer GEMM output
__device__ __nv_bfloat16 g_ah[NN * FD];       // activation split hi (GEMM input)
__device__ __nv_bfloat16 g_al[NN * FD];       // activation split lo
__device__ __nv_bfloat16 g_wth[3][FD * FD];   // W^T split hi per layer [n][k]
__device__ __nv_bfloat16 g_wtl[3][FD * FD];   // W^T split lo per layer [n][k]
__device__ float g_dinv[NN];
__device__ int   g_src[MAXE];
__device__ int   g_dst[MAXE];
__device__ int   g_cnt[NN];
__device__ int   g_tmp[NN];
__device__ int   g_bsum[128];
__device__ int   g_rowptr[NN + 1];
__device__ int   g_cursor[NN];
__device__ int2  g_csr[MAXE];                 // packed {src, __float_as_int(norm)}
__device__ int   g_is64;

// ---------------------------------------------------------------- mma helpers
__device__ __forceinline__ uint32_t smem_u32(const void* p) {
    uint32_t a;
    asm("{ .reg .u64 t; cvta.to.shared.u64 t, %1; cvt.u32.u64 %0, t; }" : "=r"(a) : "l"(p));
    return a;
}
__device__ __forceinline__ void ldm_x4(uint32_t* r, uint32_t addr) {
    asm volatile("ldmatrix.sync.aligned.m8n8.x4.shared.b16 {%0,%1,%2,%3}, [%4];"
                 : "=r"(r[0]), "=r"(r[1]), "=r"(r[2]), "=r"(r[3]) : "r"(addr));
}
__device__ __forceinline__ void mma_bf16(float* c, const uint32_t* a, uint32_t b0, uint32_t b1) {
    asm volatile(
        "mma.sync.aligned.m16n8k16.row.col.f32.bf16.bf16.f32 "
        "{%0,%1,%2,%3}, {%4,%5,%6,%7}, {%8,%9}, {%0,%1,%2,%3};"
        : "+f"(c[0]), "+f"(c[1]), "+f"(c[2]), "+f"(c[3])
        : "r"(a[0]), "r"(a[1]), "r"(a[2]), "r"(a[3]), "r"(b0), "r"(b1));
}

// ---------------------------------------------------------------- graph prep
__global__ void k_detect(const int* __restrict__ w, int E) {
    __shared__ int any;
    if (threadIdx.x == 0) any = 0;
    __syncthreads();
    int n = E < 2048 ? E : 2048;
    for (int i = threadIdx.x; i < n; i += 256)
        if (w[2 * i + 1] != 0) any = 1;
    __syncthreads();
    if (threadIdx.x == 0) g_is64 = (any ? 0 : 1);
}
__global__ void k_zero_cnt(int n) {
    int i = blockIdx.x * blockDim.x + threadIdx.x;
    if (i < n) g_cnt[i] = 0;
}
__global__ void k_convert(const int* __restrict__ w, int E) {
    int e = blockIdx.x * blockDim.x + threadIdx.x;
    if (e >= E) return;
    int s, d;
    if (g_is64) { s = w[2 * e]; d = w[2 * E + 2 * e]; }
    else        { s = w[e];     d = w[E + e]; }
    g_src[e] = s; g_dst[e] = d;
    atomicAdd(&g_cnt[d], 1);
}
__global__ void k_dinv(int n) {
    int i = blockIdx.x * blockDim.x + threadIdx.x;
    if (i < n) g_dinv[i] = rsqrtf((float)g_cnt[i] + 2.0f);
}
__global__ void k_scan1(int n) {
    __shared__ int sh[SCAN_B];
    int i = blockIdx.x * SCAN_B + threadIdx.x;
    int v = (i < n) ? g_cnt[i] : 0;
    sh[threadIdx.x] = v;
    __syncthreads();
    for (int off = 1; off < SCAN_B; off <<= 1) {
        int t = (threadIdx.x >= off) ? sh[threadIdx.x - off] : 0;
        __syncthreads();
        sh[threadIdx.x] += t;
        __syncthreads();
    }
    if (i < n) g_tmp[i] = sh[threadIdx.x] - v;
    if (threadIdx.x == SCAN_B - 1) g_bsum[blockIdx.x] = sh[SCAN_B - 1];
}
__global__ void k_scan2(int nb) {
    __shared__ int sh[128];
    int v = (threadIdx.x < nb) ? g_bsum[threadIdx.x] : 0;
    sh[threadIdx.x] = v;
    __syncthreads();
    for (int off = 1; off < 128; off <<= 1) {
        int t = (threadIdx.x >= off) ? sh[threadIdx.x - off] : 0;
        __syncthreads();
        sh[threadIdx.x] += t;
        __syncthreads();
    }
    if (threadIdx.x < nb) g_bsum[threadIdx.x] = sh[threadIdx.x] - v;
}
__global__ void k_scan3(int n, int E) {
    int i = blockIdx.x * blockDim.x + threadIdx.x;
    if (i < n) {
        int r = g_tmp[i] + g_bsum[i / SCAN_B];
        g_rowptr[i] = r;
        g_cursor[i] = r;
    }
    if (i == 0) g_rowptr[n] = E;
}
__global__ void k_fill(int E) {
    int e = blockIdx.x * blockDim.x + threadIdx.x;
    if (e >= E) return;
    int s = g_src[e], d = g_dst[e];
    int pos = atomicAdd(&g_cursor[d], 1);
    g_csr[pos] = make_int2(s, __float_as_int(g_dinv[s] * g_dinv[d]));
}

// ---------------------------------------------------------------- splits
__global__ void k_splitx(const float4* __restrict__ x, int M) {
    int i = blockIdx.x * blockDim.x + threadIdx.x;
    if (i >= M * 32) return;
    float4 v = x[i];
    __nv_bfloat16 hx = __float2bfloat16(v.x), hy = __float2bfloat16(v.y);
    __nv_bfloat16 hz = __float2bfloat16(v.z), hw = __float2bfloat16(v.w);
    __nv_bfloat162 h01, h23, l01, l23;
    h01.x = hx; h01.y = hy; h23.x = hz; h23.y = hw;
    l01.x = __float2bfloat16(v.x - __bfloat162float(hx));
    l01.y = __float2bfloat16(v.y - __bfloat162float(hy));
    l23.x = __float2bfloat16(v.z - __bfloat162float(hz));
    l23.y = __float2bfloat16(v.w - __bfloat162float(hw));
    ((__nv_bfloat162*)g_ah)[i * 2] = h01; ((__nv_bfloat162*)g_ah)[i * 2 + 1] = h23;
    ((__nv_bfloat162*)g_al)[i * 2] = l01; ((__nv_bfloat162*)g_al)[i * 2 + 1] = l23;
}
// W[k,n] -> W^T hi/lo [n,k]
__global__ void k_wsplit(const float* __restrict__ W, int layer) {
    int i = blockIdx.x * blockDim.x + threadIdx.x;
    if (i >= FD * FD) return;
    int n = i >> 7, k = i & 127;
    float w = W[k * FD + n];
    __nv_bfloat16 h = __float2bfloat16(w);
    g_wth[layer][i] = h;
    g_wtl[layer][i] = __float2bfloat16(w - __bfloat162float(h));
}

// ---------------------------------------------------------------- tensor GEMM via mma.sync
// g_h[tile] = (Ah+Al) @ (Wh+Wl)^T  via  AhWh + AlWh + AhWl  (fp32 accum)
// smem: 4 matrices of 128 rows x 272 B (128 bf16 + 8 pad)
#define ROWB 272
#define MATB (128 * ROWB)          // 34816
#define TG_SMEM (4 * MATB)         // 139264

__global__ __launch_bounds__(256, 1) void k_tgemm(int layer, int M)
{
    extern __shared__ char smem[];
    const int tid = threadIdx.x;
    const int wid = tid >> 5, lane = tid & 31;
    const int row0 = blockIdx.x * 128;

    // stage Ah, Al, Wh, Wl
    const uint4* Ah4 = (const uint4*)g_ah;
    const uint4* Al4 = (const uint4*)g_al;
    const uint4* Wh4 = (const uint4*)g_wth[layer];
    const uint4* Wl4 = (const uint4*)g_wtl[layer];
    const uint4 z4 = make_uint4(0, 0, 0, 0);
    #pragma unroll 4
    for (int i = tid; i < 2048; i += 256) {
        int r = i >> 4, c = i & 15;
        uint32_t off = (uint32_t)(r * ROWB + c * 16);
        bool ok = (row0 + r) < M;
        *(uint4*)(smem + off)            = ok ? Ah4[(row0 + r) * 16 + c] : z4;
        *(uint4*)(smem + MATB + off)     = ok ? Al4[(row0 + r) * 16 + c] : z4;
        *(uint4*)(smem + 2 * MATB + off) = Wh4[i];
        *(uint4*)(smem + 3 * MATB + off) = Wl4[i];
    }
    __syncthreads();

    const uint32_t sbase = smem_u32(smem);
    const int m0 = (wid & 3) * 32;          // warp row block
    const int n0 = (wid >> 2) * 64;         // warp col block
    const int l7 = lane & 7;

    // per-lane ldmatrix offsets (bytes), k-chunk adds kc*32
    uint32_t aoff0 = (uint32_t)((m0 + ((lane >> 3) & 1) * 8 + l7) * ROWB + (lane >> 4) * 16);
    uint32_t aoff1 = aoff0 + 16 * ROWB;
    uint32_t boff[4];
    #pragma unroll
    for (int j = 0; j < 4; j++)
        boff[j] = (uint32_t)((n0 + 16 * j + (lane >> 4) * 8 + l7) * ROWB + ((lane >> 3) & 1) * 16);

    float c[2][8][4];
    #pragma unroll
    for (int mt = 0; mt < 2; mt++)
        #pragma unroll
        for (int nt = 0; nt < 8; nt++)
            #pragma unroll
            for (int q = 0; q < 4; q++) c[mt][nt][q] = 0.f;

    #pragma unroll
    for (int p = 0; p < 3; p++) {
        uint32_t Ab = sbase + (p == 1 ? MATB : 0);
        uint32_t Wb = sbase + (p == 2 ? 3 * MATB : 2 * MATB);
        #pragma unroll
        for (int kc = 0; kc < 8; kc++) {
            uint32_t kb = (uint32_t)kc * 32;
            uint32_t a0[4], a1[4], b[4][4];
            ldm_x4(a0, Ab + aoff0 + kb);
            ldm_x4(a1, Ab + aoff1 + kb);
            #pragma unroll
            for (int j = 0; j < 4; j++) ldm_x4(b[j], Wb + boff[j] + kb);
            #pragma unroll
            for (int nt = 0; nt < 8; nt++) {
                uint32_t b0 = (nt & 1) ? b[nt >> 1][2] : b[nt >> 1][0];
                uint32_t b1 = (nt & 1) ? b[nt >> 1][3] : b[nt >> 1][1];
                mma_bf16(c[0][nt], a0, b0, b1);
                mma_bf16(c[1][nt], a1, b0, b1);
            }
        }
    }

    // epilogue: fp32 -> g_h, float2 coalesced (sector-complete per warp)
    const int g = lane >> 2, tg = lane & 3;
    #pragma unroll
    for (int mt = 0; mt < 2; mt++) {
        int rbase = row0 + m0 + mt * 16 + g;
        #pragma unroll
        for (int nt = 0; nt < 8; nt++) {
            int col = n0 + nt * 8 + tg * 2;
            if (rbase < M)
                ((float2*)g_h)[(rbase * FD + col) >> 1] = make_float2(c[mt][nt][0], c[mt][nt][1]);
            if (rbase + 8 < M)
                ((float2*)g_h)[((rbase + 8) * FD + col) >> 1] = make_float2(c[mt][nt][2], c[mt][nt][3]);
        }
    }
}

// ---------------------------------------------------------------- GEMM 128x16 (last layer)
// g_h16 = (g_ah+g_al) @ W3   (inputs already relu'd by the split writer)
__global__ __launch_bounds__(256) void k_gemm16(const float* __restrict__ W, int M)
{
    __shared__ float Ws[FD * NC];
    __shared__ float Xs[16 * FD];
    const int tid = threadIdx.x;
    const int row0 = blockIdx.x * 16;

    #pragma unroll
    for (int i = tid; i < FD * NC / 4; i += 256)
        ((float4*)Ws)[i] = ((const float4*)W)[i];
    const __nv_bfloat162* A2h = (const __nv_bfloat162*)g_ah;
    const __nv_bfloat162* A2l = (const __nv_bfloat162*)g_al;
    #pragma unroll
    for (int i = tid; i < 16 * FD / 4; i += 256) {
        int r = i >> 5, cc = i & 31;
        int gr = row0 + r;
        float4 v = make_float4(0.f, 0.f, 0.f, 0.f);
        if (gr < M) {
            int idx = gr * 64 + cc * 2;
            __nv_bfloat162 h0 = A2h[idx], l0 = A2l[idx];
            __nv_bfloat162 h1 = A2h[idx + 1], l1 = A2l[idx + 1];
            v.x = __bfloat162float(h0.x) + __bfloat162float(l0.x);
            v.y = __bfloat162float(h0.y) + __bfloat162float(l0.y);
            v.z = __bfloat162float(h1.x) + __bfloat162float(l1.x);
            v.w = __bfloat162float(h1.y) + __bfloat162float(l1.y);
        }
        ((float4*)Xs)[i] = v;
    }
    __syncthreads();

    const int r = tid >> 4, cc = tid & 15;
    float acc = 0.f;
    #pragma unroll 8
    for (int k = 0; k < FD; k++) acc += Xs[r * FD + k] * Ws[k * NC + cc];

    int gr = row0 + r;
    if (gr < M) g_h16[gr * NC + cc] = acc;
}

// ---------------------------------------------------------------- fused aggregate (CSR)
// warp per node: a = b + 2*dinv^2*h[n] + sum norm_e*h[src_e]; write relu'd bf16 split
__global__ __launch_bounds__(256) void k_agg128(const float4* __restrict__ b, int N)
{
    int warp = (blockIdx.x * blockDim.x + threadIdx.x) >> 5;
    int lane = threadIdx.x & 31;
    if (warp >= N) return;
    int beg = g_rowptr[warp], end = g_rowptr[warp + 1];
    float dv = g_dinv[warp];
    float s = 2.0f * dv * dv;
    const float4* h4 = (const float4*)g_h;

    float4 acc = h4[warp * 32 + lane];
    float4 bv = b[lane];
    acc.x = acc.x * s + bv.x; acc.y = acc.y * s + bv.y;
    acc.z = acc.z * s + bv.z; acc.w = acc.w * s + bv.w;

    int e = beg;
    for (; e + 1 < end; e += 2) {
        int2 c0 = g_csr[e], c1 = g_csr[e + 1];
        float4 v0 = h4[c0.x * 32 + lane];
        float4 v1 = h4[c1.x * 32 + lane];
        float n0 = __int_as_float(c0.y), n1 = __int_as_float(c1.y);
        acc.x += n0 * v0.x + n1 * v1.x;
        acc.y += n0 * v0.y + n1 * v1.y;
        acc.z += n0 * v0.z + n1 * v1.z;
        acc.w += n0 * v0.w + n1 * v1.w;
    }
    if (e < end) {
        int2 c0 = g_csr[e];
        float4 v0 = h4[c0.x * 32 + lane];
        float n0 = __int_as_float(c0.y);
        acc.x += n0 * v0.x; acc.y += n0 * v0.y;
        acc.z += n0 * v0.z; acc.w += n0 * v0.w;
    }

    // relu + bf16 hi/lo split for next GEMM
    float tx = fmaxf(acc.x, 0.f), ty = fmaxf(acc.y, 0.f);
    float tz = fmaxf(acc.z, 0.f), tw = fmaxf(acc.w, 0.f);
    __nv_bfloat16 hx = __float2bfloat16(tx), hy = __float2bfloat16(ty);
    __nv_bfloat16 hz = __float2bfloat16(tz), hw = __float2bfloat16(tw);
    __nv_bfloat162 h01, h23, l01, l23;
    h01.x = hx; h01.y = hy; h23.x = hz; h23.y = hw;
    l01.x = __float2bfloat16(tx - __bfloat162float(hx));
    l01.y = __float2bfloat16(ty - __bfloat162float(hy));
    l23.x = __float2bfloat16(tz - __bfloat162float(hz));
    l23.y = __float2bfloat16(tw - __bfloat162float(hw));
    int base = warp * 64 + lane * 2;
    ((__nv_bfloat162*)g_ah)[base] = h01; ((__nv_bfloat162*)g_ah)[base + 1] = h23;
    ((__nv_bfloat162*)g_al)[base] = l01; ((__nv_bfloat162*)g_al)[base + 1] = l23;
}

// last layer: 4 lanes per node, fused bias + self-loop + aggregate + tanh -> out
__global__ __launch_bounds__(256) void k_agg16(const float4* __restrict__ b,
                                               float4* __restrict__ out, int N)
{
    int t = blockIdx.x * blockDim.x + threadIdx.x;
    int node = t >> 2, q = t & 3;
    if (node >= N) return;
    int beg = g_rowptr[node], end = g_rowptr[node + 1];
    float dv = g_dinv[node];
    float s = 2.0f * dv * dv;
    const float4* h4 = (const float4*)g_h16;

    float4 acc = h4[node * 4 + q];
    float4 bv = b[q];
    acc.x = acc.x * s + bv.x; acc.y = acc.y * s + bv.y;
    acc.z = acc.z * s + bv.z; acc.w = acc.w * s + bv.w;

    for (int e = beg; e < end; e++) {
        int2 cc = g_csr[e];
        float4 v = h4[cc.x * 4 + q];
        float n = __int_as_float(cc.y);
        acc.x += n * v.x; acc.y += n * v.y;
        acc.z += n * v.z; acc.w += n * v.w;
    }
    acc.x = tanhf(acc.x); acc.y = tanhf(acc.y);
    acc.z = tanhf(acc.z); acc.w = tanhf(acc.w);
    out[node * 4 + q] = acc;
}

// ---------------------------------------------------------------- launch
extern "C" void kernel_launch(void* const* d_in, const int* in_sizes, int n_in,
                              void* d_out, int out_size)
{
    const float* x  = (const float*)d_in[0];
    const int*   ew = (const int*)d_in[1];
    const float* W0 = (const float*)d_in[2];
    const float* b0 = (const float*)d_in[3];
    const float* W1 = (const float*)d_in[4];
    const float* b1 = (const float*)d_in[5];
    const float* W2 = (const float*)d_in[6];
    const float* b2 = (const float*)d_in[7];
    const float* W3 = (const float*)d_in[8];
    const float* b3 = (const float*)d_in[9];
    float* out = (float*)d_out;

    const int E = in_sizes[1] / 2;
    const int M = in_sizes[0] / FD;

    cudaFuncSetAttribute(k_tgemm, cudaFuncAttributeMaxDynamicSharedMemorySize, TG_SMEM);

    // ---- graph + weight/input prep ----
    const int nb = (M + SCAN_B - 1) / SCAN_B;
    k_detect<<<1, 256>>>(ew, E);
    k_zero_cnt<<<(M + 255) / 256, 256>>>(M);
    k_convert<<<(E + 255) / 256, 256>>>(ew, E);
    k_dinv<<<(M + 255) / 256, 256>>>(M);
    k_scan1<<<nb, SCAN_B>>>(M);
    k_scan2<<<1, 128>>>(nb);
    k_scan3<<<(M + 255) / 256, 256>>>(M, E);
    k_fill<<<(E + 255) / 256, 256>>>(E);
    k_wsplit<<<64, 256>>>(W0, 0);
    k_wsplit<<<64, 256>>>(W1, 1);
    k_wsplit<<<64, 256>>>(W2, 2);
    k_splitx<<<(M * 32 + 255) / 256, 256>>>((const float4*)x, M);

    const int gT = (M + 127) / 128;
    const int gAgg128 = (M * 32 + 255) / 256;
    const int gAgg16  = (M * 4 + 255) / 256;

    // Layer 0
    k_tgemm<<<gT, 256, TG_SMEM>>>(0, M);
    k_agg128<<<gAgg128, 256>>>((const float4*)b0, M);
    // Layer 1
    k_tgemm<<<gT, 256, TG_SMEM>>>(1, M);
    k_agg128<<<gAgg128, 256>>>((const float4*)b1, M);
    // Layer 2
    k_tgemm<<<gT, 256, TG_SMEM>>>(2, M);
    k_agg128<<<gAgg128, 256>>>((const float4*)b2, M);
    // Layer 3 (16-wide) fused: gemm -> aggregate+bias+tanh -> out
    k_gemm16<<<(M + 15) / 16, 256>>>(W3, M);
    k_agg16<<<gAgg16, 256>>>((const float4*)b3, (float4*)out, M);
}